// round 15
// baseline (speedup 1.0000x reference)
#include <cuda_runtime.h>
#include <cuda_bf16.h>
#include <cuda_fp16.h>
#include <cstdint>

#define K_CODES 1024
#define DIM 64
#define N_PTS 131072
#define GAMMA_F 0.99f
#define ONE_M_GAMMA 0.01f
#define ALPHA_F 1e-9f
#define BETA_F 0.25f

#define CCHUNK 128              // codes per smem chunk (double-buffered)
#define ROW_PITCH 144           // bytes per code row in smem (64*2 + 16 pad)
#define SPLIT_STRIDE (CCHUNK * ROW_PITCH)        // 18432
#define ESQ_OFF (2 * SPLIT_STRIDE)               // 36864
#define BUF_SZ (ESQ_OFF + CCHUNK * 4)            // 37376
#define SM_RED (2 * BUF_SZ)                      // 74752
#define SM_TOTAL (SM_RED + 128 * 4)              // 75264
#define NCHUNKS (K_CODES / CCHUNK)               // 8

// ---- scratch (__device__ globals; no allocs) ----
__device__ __align__(16) __half g_Es0[K_CODES * DIM];
__device__ __align__(16) __half g_Es1[K_CODES * DIM];
__device__ __align__(16) float g_esq[K_CODES];
__device__ float g_counts[K_CODES];
__device__ float g_sums[K_CODES * DIM];
__device__ float g_loss;
__device__ float g_cs_inv[K_CODES];

// mma.sync m16n8k16 fp16 -> f32 (sm_80+ baseline; valid at compute_103)
#define MMA16816(d, a, b0v, b1v, c)                                          \
    asm volatile("mma.sync.aligned.m16n8k16.row.col.f32.f16.f16.f32 "        \
        "{%0,%1,%2,%3}, {%4,%5,%6,%7}, {%8,%9}, {%10,%11,%12,%13};"          \
        : "=f"((d)[0]), "=f"((d)[1]), "=f"((d)[2]), "=f"((d)[3])             \
        : "r"((a)[0]), "r"((a)[1]), "r"((a)[2]), "r"((a)[3]),                \
          "r"(b0v), "r"(b1v),                                                \
          "f"((c)[0]), "f"((c)[1]), "f"((c)[2]), "f"((c)[3]))

#define LDSM_X4(r, addr)                                                     \
    asm volatile("ldmatrix.sync.aligned.m8n8.x4.shared.b16 {%0,%1,%2,%3}, [%4];" \
        : "=r"((r)[0]), "=r"((r)[1]), "=r"((r)[2]), "=r"((r)[3])             \
        : "r"(addr))

#define CP_ASYNC16(dst, src)                                                 \
    asm volatile("cp.async.cg.shared.global [%0], [%1], 16;"                 \
        :: "r"(dst), "l"(src))
#define CP_COMMIT()  asm volatile("cp.async.commit_group;" ::: "memory")
#define CP_WAIT(n)   asm volatile("cp.async.wait_group %0;" :: "n"(n) : "memory")

__device__ __forceinline__ uint32_t smem_u32(const void* p) {
    uint32_t a;
    asm("{ .reg .u64 t; cvta.to.shared.u64 t, %1; cvt.u32.u64 %0, t; }"
        : "=r"(a) : "l"(p));
    return a;
}
__device__ __forceinline__ unsigned pack_h2(__half lo, __half hi) {
    __half2 v = __halves2half2(lo, hi);
    return *(unsigned*)&v;
}

// ---------------------------------------------------------------------------
// prep_E: 2-term fp16 splits of e + esq, + zero stats.  grid = K*DIM/256.
// ---------------------------------------------------------------------------
__global__ void prep_E(const float* __restrict__ E) {
    __shared__ float ws[8];
    int e = blockIdx.x * 256 + threadIdx.x;
    float v = E[e];

    __half h0 = __float2half(v);
    float r1 = v - __half2float(h0);
    __half h1 = __float2half(r1);
    g_Es0[e] = h0; g_Es1[e] = h1;

    g_sums[e] = 0.0f;
    if (e < K_CODES) g_counts[e] = 0.0f;
    if (e == 0) g_loss = 0.0f;

    float sq = v * v;
    #pragma unroll
    for (int o = 16; o > 0; o >>= 1) sq += __shfl_xor_sync(0xffffffffu, sq, o);
    if ((threadIdx.x & 31) == 0) ws[threadIdx.x >> 5] = sq;
    __syncthreads();
    if ((threadIdx.x & 63) == 0) {
        int g = threadIdx.x >> 6;
        g_esq[e >> 6] = ws[2 * g] + ws[2 * g + 1];
    }
}

// ---------------------------------------------------------------------------
// dist kernel: HMMA fp16 2-split (3 products, big+small accumulator chains),
// 32 rows per warp (2 M-tiles), key = esq - 2*x.e, argmin + stats + gather.
// 128 threads = 4 warps x 32 points = 128 points/CTA. grid = N/128.
// Precision note: the small-product terms (x0*e1, x1*e0) MUST accumulate
// separately from the big x0*e0 chain so they round at small magnitude.
// ---------------------------------------------------------------------------
__global__ void __launch_bounds__(128, 3)
dist_kernel(const float* __restrict__ X, const float* __restrict__ E,
            float4* __restrict__ out_z,
            float* __restrict__ out_arg, float* __restrict__ out_mind) {
    extern __shared__ char smem[];
    const uint32_t sbase = smem_u32(smem);
    const int tid = threadIdx.x;
    const int wid = tid >> 5;
    const int lane = tid & 31;
    const int g = lane >> 2;          // 0..7
    const int q = lane & 3;           // 0..3
    const int tileRow = blockIdx.x * 128 + wid * 32;

    // per-lane ldmatrix row offset (tile t = lane>>3, row r = lane&7)
    const int lt = lane >> 3;
    const int lr = lane & 7;
    const uint32_t rowoff = (uint32_t)(lr * ROW_PITCH + (lt >> 1) * 32 + (lt & 1) * 16);

    // ---- kick off chunk-0 B staging before doing A-split math ----
    const __half* es[2] = {g_Es0, g_Es1};
    auto stage = [&](int chunk) {
        uint32_t bb = sbase + (uint32_t)((chunk & 1) * BUF_SZ);
        #pragma unroll
        for (int ii = 0; ii < 16; ii++) {
            int i = tid + ii * 128;       // 0..2047 = 2 splits x 1024 uint4
            int s = i >> 10;
            int r = i & 1023;
            int n = r >> 3, c = r & 7;
            CP_ASYNC16(bb + s * SPLIT_STRIDE + n * ROW_PITCH + c * 16,
                       es[s] + (size_t)chunk * CCHUNK * DIM + r * 8);
        }
        if (tid < CCHUNK / 4)
            CP_ASYNC16(bb + ESQ_OFF + tid * 16, g_esq + chunk * CCHUNK + tid * 4);
        CP_COMMIT();
    };
    stage(0);

    // ---- A fragments in-register from X (2-way fp16 split of -2x), 2 tiles --
    unsigned A[2][2][4][4];        // [tile][split][kc][reg]
    float xsq[2][2];               // [tile][half: row g / row g+8]
    #pragma unroll
    for (int t = 0; t < 2; t++) {
        const int r0 = tileRow + t * 16 + g;
        const int r1 = r0 + 8;
        float s0 = 0.0f, s1 = 0.0f;
        #pragma unroll
        for (int kc = 0; kc < 4; kc++) {
            float2 v00 = *(const float2*)(X + (size_t)r0 * DIM + kc * 16 + q * 2);
            float2 v01 = *(const float2*)(X + (size_t)r0 * DIM + kc * 16 + q * 2 + 8);
            float2 v10 = *(const float2*)(X + (size_t)r1 * DIM + kc * 16 + q * 2);
            float2 v11 = *(const float2*)(X + (size_t)r1 * DIM + kc * 16 + q * 2 + 8);
            s0 += v00.x * v00.x + v00.y * v00.y + v01.x * v01.x + v01.y * v01.y;
            s1 += v10.x * v10.x + v10.y * v10.y + v11.x * v11.x + v11.y * v11.y;

            const float2 vs[4] = {v00, v10, v01, v11};
            #pragma unroll
            for (int j = 0; j < 4; j++) {
                float ax = -2.0f * vs[j].x, ay = -2.0f * vs[j].y;
                __half x0 = __float2half(ax);
                __half x1 = __float2half(ax - __half2float(x0));
                __half y0 = __float2half(ay);
                __half y1 = __float2half(ay - __half2float(y0));
                A[t][0][kc][j] = pack_h2(x0, y0);
                A[t][1][kc][j] = pack_h2(x1, y1);
            }
        }
        // quad-lane reduce (4 lanes hold disjoint 16-col subsets)
        s0 += __shfl_xor_sync(0xffffffffu, s0, 1);
        s0 += __shfl_xor_sync(0xffffffffu, s0, 2);
        s1 += __shfl_xor_sync(0xffffffffu, s1, 1);
        s1 += __shfl_xor_sync(0xffffffffu, s1, 2);
        xsq[t][0] = s0;
        xsq[t][1] = s1;
    }

    float zero4[4] = {0.0f, 0.0f, 0.0f, 0.0f};
    float best[2][2] = {{3.4e38f, 3.4e38f}, {3.4e38f, 3.4e38f}};
    int   bidx[2][2] = {{0, 0}, {0, 0}};

    for (int chunk = 0; chunk < NCHUNKS; chunk++) {
        if (chunk + 1 < NCHUNKS) { stage(chunk + 1); CP_WAIT(1); }
        else                     { CP_WAIT(0); }
        __syncthreads();

        const uint32_t bb = sbase + (uint32_t)((chunk & 1) * BUF_SZ);
        const char* ebase = smem + (chunk & 1) * BUF_SZ + ESQ_OFF;

        #pragma unroll
        for (int nb = 0; nb < CCHUNK / 8; nb++) {
            unsigned B0[8], B1[8];
            {
                uint32_t a = bb + (uint32_t)(nb * 8 * ROW_PITCH) + rowoff;
                LDSM_X4(B0, a);
                LDSM_X4(B0 + 4, a + 64);
                a += SPLIT_STRIDE;
                LDSM_X4(B1, a);
                LDSM_X4(B1 + 4, a + 64);
            }

            // big chain: x0*e0 (large magnitude); small chain: x0*e1 + x1*e0
            // (uniformly small magnitude -> accurate accumulation)
            float accB[2][4], accS[2][4];
            #pragma unroll
            for (int kc = 0; kc < 4; kc++) {
                unsigned b00 = B0[2 * kc], b01 = B0[2 * kc + 1];
                unsigned b10 = B1[2 * kc], b11 = B1[2 * kc + 1];
                #pragma unroll
                for (int t = 0; t < 2; t++) {
                    MMA16816(accB[t], A[t][0][kc], b00, b01,
                             kc == 0 ? zero4 : accB[t]);          // x0*e0
                    MMA16816(accS[t], A[t][0][kc], b10, b11,
                             kc == 0 ? zero4 : accS[t]);          // x0*e1
                    MMA16816(accS[t], A[t][1][kc], b00, b01, accS[t]); // x1*e0
                }
            }

            float2 eq = *(const float2*)(ebase + (nb * 8 + 2 * q) * 4);
            int col = chunk * CCHUNK + nb * 8 + 2 * q;
            #pragma unroll
            for (int t = 0; t < 2; t++) {
                float k0 = accB[t][0] + (accS[t][0] + eq.x);
                float k1 = accB[t][1] + (accS[t][1] + eq.y);
                float k2 = accB[t][2] + (accS[t][2] + eq.x);
                float k3 = accB[t][3] + (accS[t][3] + eq.y);
                if (k0 < best[t][0]) { best[t][0] = k0; bidx[t][0] = col; }
                if (k1 < best[t][0]) { best[t][0] = k1; bidx[t][0] = col + 1; }
                if (k2 < best[t][1]) { best[t][1] = k2; bidx[t][1] = col; }
                if (k3 < best[t][1]) { best[t][1] = k3; bidx[t][1] = col + 1; }
            }
        }
        __syncthreads();   // buffer (chunk&1) free for prefetch at chunk+1
    }

    // ---- combine across the 4 quad lanes (cols), tie -> lower index ----
    #pragma unroll
    for (int t = 0; t < 2; t++) {
        #pragma unroll
        for (int h = 0; h < 2; h++) {
            #pragma unroll
            for (int o = 1; o < 4; o <<= 1) {
                float ob = __shfl_xor_sync(0xffffffffu, best[t][h], o);
                int   oi = __shfl_xor_sync(0xffffffffu, bidx[t][h], o);
                if (ob < best[t][h] || (ob == best[t][h] && oi < bidx[t][h])) {
                    best[t][h] = ob; bidx[t][h] = oi;
                }
            }
        }
    }

    // ---- fused gather + outputs + stats for 4 rows per thread-group ----
    float lsum = 0.0f;
    #pragma unroll
    for (int t = 0; t < 2; t++) {
        #pragma unroll
        for (int h = 0; h < 2; h++) {
            const int row = tileRow + t * 16 + h * 8 + g;
            const int id  = bidx[t][h];
            // gather: all 4 quad lanes copy E[id] row to Z
            const float4* ee = (const float4*)E + (size_t)id * 16;
            float4* zz = out_z + (size_t)row * 16;
            #pragma unroll
            for (int j = 0; j < 4; j++) zz[q + 4 * j] = ee[q + 4 * j];

            if (q == 0) {
                float m = xsq[t][h] + best[t][h];
                out_arg[row]  = (float)id;
                out_mind[row] = m;
                atomicAdd(&g_counts[id], 1.0f);
                lsum += m;
                const float4* xr = (const float4*)(X + (size_t)row * DIM);
                float* sp = &g_sums[(size_t)id * DIM];
                #pragma unroll
                for (int j = 0; j < 16; j++) {
                    float4 v = xr[j];
                    asm volatile("red.global.add.v4.f32 [%0], {%1,%2,%3,%4};"
                                 :: "l"(sp + 4 * j),
                                    "f"(v.x), "f"(v.y), "f"(v.z), "f"(v.w)
                                 : "memory");
                }
            }
        }
    }

    float* sred = (float*)(smem + SM_RED);
    __syncthreads();
    sred[tid] = lsum;
    __syncthreads();
    for (int s = 64; s > 0; s >>= 1) {
        if (tid < s) sred[tid] += sred[tid + s];
        __syncthreads();
    }
    if (tid == 0) atomicAdd(&g_loss, sred[0]);
}

// ---------------------------------------------------------------------------
// cs + loss
// ---------------------------------------------------------------------------
__global__ void cs_kernel(const float* __restrict__ cluster_sizes,
                          float* __restrict__ out_loss, float* __restrict__ out_cs) {
    __shared__ float warp_sums[32];
    int k = threadIdx.x;
    float cs_pre = GAMMA_F * cluster_sizes[k] + ONE_M_GAMMA * g_counts[k];
    float v = cs_pre;
    #pragma unroll
    for (int o = 16; o > 0; o >>= 1) v += __shfl_xor_sync(0xffffffffu, v, o);
    if ((k & 31) == 0) warp_sums[k >> 5] = v;
    __syncthreads();
    if (k < 32) {
        float w = warp_sums[k];
        #pragma unroll
        for (int o = 16; o > 0; o >>= 1) w += __shfl_xor_sync(0xffffffffu, w, o);
        if (k == 0) warp_sums[0] = w;
    }
    __syncthreads();
    float total = warp_sums[0];
    float denom = 1.0f + ALPHA_F * (float)K_CODES / total;
    float cs = (cs_pre + ALPHA_F) / denom;
    out_cs[k]   = cs;
    g_cs_inv[k] = 1.0f / cs;
    if (k == 0) out_loss[0] = BETA_F * g_loss / (float)N_PTS;
}

// ---------------------------------------------------------------------------
// ma + E_new
// ---------------------------------------------------------------------------
__global__ void ema_kernel(const float* __restrict__ moving_avg,
                           float* __restrict__ out_enew, float* __restrict__ out_ma) {
    int i = blockIdx.x * 256 + threadIdx.x;
    int k = i >> 6;
    float ma = GAMMA_F * moving_avg[i] + ONE_M_GAMMA * g_sums[i];
    out_ma[i]   = ma;
    out_enew[i] = ma * g_cs_inv[k];
}

// ---------------------------------------------------------------------------
// launch
// ---------------------------------------------------------------------------
extern "C" void kernel_launch(void* const* d_in, const int* in_sizes, int n_in,
                              void* d_out, int out_size) {
    const float* X    = (const float*)d_in[0];
    const float* E    = (const float*)d_in[1];
    const float* cssz = (const float*)d_in[2];
    const float* mavg = (const float*)d_in[3];

    float* out = (float*)d_out;
    float* out_z    = out;
    float* out_loss = out + (size_t)N_PTS * DIM;
    float* out_arg  = out_loss + 1;
    float* out_mind = out_arg + N_PTS;
    float* out_enew = out_mind + N_PTS;
    float* out_cs   = out_enew + K_CODES * DIM;
    float* out_ma   = out_cs + K_CODES;

    static bool attr_done = false;
    if (!attr_done) {
        cudaFuncSetAttribute(dist_kernel,
                             cudaFuncAttributeMaxDynamicSharedMemorySize, SM_TOTAL);
        attr_done = true;
    }

    prep_E<<<(K_CODES * DIM) / 256, 256>>>(E);
    dist_kernel<<<N_PTS / 128, 128, SM_TOTAL>>>(X, E, (float4*)out_z,
                                                out_arg, out_mind);
    cs_kernel<<<1, 1024>>>(cssz, out_loss, out_cs);
    ema_kernel<<<(K_CODES * DIM) / 256, 256>>>(mavg, out_enew, out_ma);
}